// round 5
// baseline (speedup 1.0000x reference)
#include <cuda_runtime.h>
#include <math.h>

#define BB 2
#define PP 8192
#define KK 20
#define NT 128
#define GX 7
#define GY 7
#define GZ 20
#define NCELL (GX * GY * GZ)
#define CELLSZ 3.0f
#define INV_CELL (1.0f / 3.0f)
#define OXC (-10.0f)
#define OYC (-10.0f)
#define OZC (1.0f)

__device__ double g_acc[2];
__device__ unsigned g_done;
__device__ int g_cnt_cells[4 * NCELL];
__device__ int g_cur[4 * NCELL];
__device__ int g_off[4 * (NCELL + 1)];
__device__ float4 g_pts[4 * PP];   // reordered db points per (side,batch); .w = orig idx bits

__device__ __forceinline__ void cell_coords(float x, float y, float z,
                                            int& ix, int& iy, int& iz) {
    ix = min(GX - 1, max(0, (int)floorf((x - OXC) * INV_CELL)));
    iy = min(GY - 1, max(0, (int)floorf((y - OYC) * INV_CELL)));
    iz = min(GZ - 1, max(0, (int)floorf((z - OZC) * INV_CELL)));
}

__global__ void init_kernel() {
    int t = threadIdx.x;
    if (t == 0) { g_acc[0] = 0.0; g_acc[1] = 0.0; g_done = 0u; }
    for (int i = t; i < 4 * NCELL; i += blockDim.x) g_cnt_cells[i] = 0;
}

// Count points per cell. Grid: (BB*PP/256, 2 sides).
__global__ void count_kernel(const float* __restrict__ xyz1, const float* __restrict__ xyz2,
                             const int* __restrict__ npts1, const int* __restrict__ npts2) {
    const int s = blockIdx.y;
    const int gi = blockIdx.x * blockDim.x + threadIdx.x;
    const int b = gi >> 13;
    const int i = gi & (PP - 1);
    const float* src = s ? xyz1 : xyz2;             // db side s
    const int ldb = (s ? npts1 : npts2)[b];
    if (i >= ldb) return;
    int g3 = 3 * gi;
    int ix, iy, iz;
    cell_coords(src[g3], src[g3 + 1], src[g3 + 2], ix, iy, iz);
    int c = (iz * GY + iy) * GX + ix;
    atomicAdd(&g_cnt_cells[(s * BB + b) * NCELL + c], 1);
}

// Per-set prefix sum (4 blocks, one per set). Writes offsets + fill cursors.
__global__ void scan_kernel() {
    __shared__ int sv[1024];
    const int set = blockIdx.x;
    const int t = threadIdx.x;
    int v = (t < NCELL) ? g_cnt_cells[set * NCELL + t] : 0;
    sv[t] = v;
    __syncthreads();
    for (int o = 1; o < 1024; o <<= 1) {
        int a = (t >= o) ? sv[t - o] : 0;
        __syncthreads();
        sv[t] += a;
        __syncthreads();
    }
    if (t < NCELL) {
        g_off[set * (NCELL + 1) + t + 1] = sv[t];
        g_cur[set * NCELL + t] = sv[t] - v;
        if (t == 0) g_off[set * (NCELL + 1)] = 0;
    }
}

// Scatter points into cell-sorted order (float4 with orig idx in .w).
__global__ void fill_kernel(const float* __restrict__ xyz1, const float* __restrict__ xyz2,
                            const int* __restrict__ npts1, const int* __restrict__ npts2) {
    const int s = blockIdx.y;
    const int gi = blockIdx.x * blockDim.x + threadIdx.x;
    const int b = gi >> 13;
    const int i = gi & (PP - 1);
    const float* src = s ? xyz1 : xyz2;
    const int ldb = (s ? npts1 : npts2)[b];
    if (i >= ldb) return;
    int g3 = 3 * gi;
    float x = src[g3], y = src[g3 + 1], z = src[g3 + 2];
    int ix, iy, iz;
    cell_coords(x, y, z, ix, iy, iz);
    int c = (iz * GY + iy) * GX + ix;
    int set = s * BB + b;
    int pos = atomicAdd(&g_cur[set * NCELL + c], 1);
    g_pts[set * PP + pos] = make_float4(x, y, z, __int_as_float(i));
}

// One thread per query: transform into raw db frame, expanding-shell exact top-20,
// exact epilogue, block reduce, last-block finalize.
__global__ __launch_bounds__(NT) void query_kernel(
    const float* __restrict__ xyz1, const float* __restrict__ hsv1,
    const float* __restrict__ normal1, const float* __restrict__ nres1,
    const float* __restrict__ xyz2, const float* __restrict__ hsv2,
    const float* __restrict__ normal2, const float* __restrict__ nres2,
    const float* __restrict__ R12, const float* __restrict__ t12,
    const float* __restrict__ R21, const float* __restrict__ t21,
    const int* __restrict__ npts1, const int* __restrict__ npts2,
    float* __restrict__ out)
{
    const int s = blockIdx.y;
    const int tid = threadIdx.x;
    const int qi = blockIdx.x * NT + tid;
    const int b = qi >> 13;
    const int p_local = qi & (PP - 1);
    const int boff = b * PP;
    const int set = s * BB + b;

    const float* xq  = s ? xyz2 : xyz1;
    const float* hq  = s ? hsv2 : hsv1;
    const float* nq  = s ? normal2 : normal1;
    const float* rq  = s ? nres2 : nres1;
    const float* xdb = s ? xyz1 : xyz2;      // raw db
    const float* ndb = s ? normal1 : normal2;
    const float* hdb = s ? hsv1 : hsv2;
    const float* rdb = s ? nres1 : nres2;
    const float* Rm  = (s ? R21 : R12) + b * 9;
    const float* tv  = (s ? t21 : t12) + b * 3;
    const int lq = (s ? npts2 : npts1)[b];

    float sum = 0.f;
    if (p_local < lq) {
        const float R0 = Rm[0], R1 = Rm[1], R2 = Rm[2];
        const float R3 = Rm[3], R4 = Rm[4], R5 = Rm[5];
        const float R6 = Rm[6], R7 = Rm[7], R8 = Rm[8];
        const float ux = xq[3 * qi + 0] - tv[0];
        const float uy = xq[3 * qi + 1] - tv[1];
        const float uz = xq[3 * qi + 2] - tv[2];
        // q' = R^T (q - t): distance-equivalent query in raw db frame
        const float qpx = fmaf(R0, ux, fmaf(R3, uy, R6 * uz));
        const float qpy = fmaf(R1, ux, fmaf(R4, uy, R7 * uz));
        const float qpz = fmaf(R2, ux, fmaf(R5, uy, R8 * uz));

        int cx, cy, cz;
        cell_coords(qpx, qpy, qpz, cx, cy, cz);

        float keys[KK];
#pragma unroll
        for (int k = 0; k < KK; k++) keys[k] = 3.0e38f;
        float thr = 3.0e38f;

        const int cbase = set * (NCELL + 1);
        const float4* __restrict__ pts = g_pts + set * PP;

        for (int sr = 0; sr < 32; sr++) {
            const int zlo = max(cz - sr, 0), zhi = min(cz + sr, GZ - 1);
            const int ylo = max(cy - sr, 0), yhi = min(cy + sr, GY - 1);
            const int xlo = max(cx - sr, 0), xhi = min(cx + sr, GX - 1);
            for (int z = zlo; z <= zhi; z++) {
                bool zface = (z == cz - sr) || (z == cz + sr);
                for (int y = ylo; y <= yhi; y++) {
                    bool face = zface || (y == cy - sr) || (y == cy + sr);
                    for (int x = xlo; x <= xhi; x++) {
                        if (!face && x != cx - sr && x != cx + sr) continue;
                        int c = (z * GY + y) * GX + x;
                        int j0 = g_off[cbase + c];
                        int j1 = g_off[cbase + c + 1];
                        for (int j = j0; j < j1; j++) {
                            float4 p = pts[j];
                            float dx = qpx - p.x, dy = qpy - p.y, dz = qpz - p.z;
                            float d2 = fmaf(dx, dx, fmaf(dy, dy, dz * dz));
                            if (d2 < thr) {
                                unsigned io = ((unsigned)__float_as_int(p.w)) & 8191u;
                                float xk = __uint_as_float(
                                    (__float_as_uint(d2) & 0xFFFFE000u) | io);
#pragma unroll
                                for (int k = 0; k < KK; k++) {
                                    float lo = fminf(xk, keys[k]);
                                    xk = fmaxf(xk, keys[k]);
                                    keys[k] = lo;
                                }
                                thr = keys[KK - 1];
                            }
                        }
                    }
                }
            }
            // Conservative stop: clearance from q' to faces of visited cube
            // (faces at grid border -> no points beyond -> ignore).
            float dm = 1e30f;
            if (cx - sr > 0)      dm = fminf(dm, qpx - (OXC + (float)(cx - sr) * CELLSZ));
            if (cx + sr < GX - 1) dm = fminf(dm, (OXC + (float)(cx + sr + 1) * CELLSZ) - qpx);
            if (cy - sr > 0)      dm = fminf(dm, qpy - (OYC + (float)(cy - sr) * CELLSZ));
            if (cy + sr < GY - 1) dm = fminf(dm, (OYC + (float)(cy + sr + 1) * CELLSZ) - qpy);
            if (cz - sr > 0)      dm = fminf(dm, qpz - (OZC + (float)(cz - sr) * CELLSZ));
            if (cz + sr < GZ - 1) dm = fminf(dm, (OZC + (float)(cz + sr + 1) * CELLSZ) - qpz);
            if (dm > 9.0e29f) break;                  // cube covers whole grid
            dm = fmaxf(dm, 0.0f);
            if (thr <= dm * dm * 0.999f) break;       // margin covers key truncation
        }

        // Exact epilogue over the 20 winners (raw-frame distances; nq rotated by R^T).
        const float qz_own = xq[3 * qi + 2];
        float ell = fmaxf(0.015f * (qz_own - 10.0f), 0.15f);
        float inv_ls = 1.0f / (ell * ell);
        float hx = hq[3 * qi + 0], hy = hq[3 * qi + 1], hz = hq[3 * qi + 2];
        float nxr = nq[3 * qi + 0], nyr = nq[3 * qi + 1], nzr = nq[3 * qi + 2];
        float npx = fmaf(R0, nxr, fmaf(R3, nyr, R6 * nzr));
        float npy = fmaf(R1, nxr, fmaf(R4, nyr, R7 * nzr));
        float npz = fmaf(R2, nxr, fmaf(R5, nyr, R8 * nzr));
        float rqv = rq[qi];
#pragma unroll
        for (int k = 0; k < KK; k++) {
            int idx = (int)(__float_as_uint(keys[k]) & 8191u);
            int g3 = 3 * (boff + idx);
            float dx = qpx - xdb[g3 + 0];
            float dy = qpy - xdb[g3 + 1];
            float dz = qpz - xdb[g3 + 2];
            float d2 = fmaf(dx, dx, fmaf(dy, dy, dz * dz));
            float ndot = fmaf(npx, ndb[g3 + 0], fmaf(npy, ndb[g3 + 1], npz * ndb[g3 + 2]));
            float chx = hx - hdb[g3 + 0];
            float chy = hy - hdb[g3 + 1];
            float chz = hz - hdb[g3 + 2];
            float cd = sqrtf(fmaf(chx, chx, fmaf(chy, chy, chz * chz)) + 1e-12f);
            float rk = rdb[boff + idx];
            float alpha = 0.2f / (0.1f + rqv + rk);
            float nk = fmaxf(ndot * alpha, 0.0f);
            sum += __expf(-(d2 * inv_ls + cd * 5.0f)) * nk;
        }
    }

    // Warp + block reduce, one double atomic per block; last block finalizes.
#pragma unroll
    for (int o = 16; o > 0; o >>= 1) sum += __shfl_down_sync(0xffffffffu, sum, o);
    __shared__ float wsum[NT / 32];
    if ((tid & 31) == 0) wsum[tid >> 5] = sum;
    __syncthreads();
    if (tid == 0) {
        float bs = 0.f;
#pragma unroll
        for (int w = 0; w < NT / 32; w++) bs += wsum[w];
        atomicAdd(&g_acc[s], (double)bs);
        __threadfence();
        unsigned done = atomicAdd(&g_done, 1u);
        if (done == (unsigned)(gridDim.x * gridDim.y) - 1u) {
            double s1 = (double)npts1[0] + (double)npts1[1];
            double s2 = (double)npts2[0] + (double)npts2[1];
            double k1 = g_acc[0] / (s1 * (double)KK);
            double k2 = g_acc[1] / (s2 * (double)KK);
            out[0] = (float)(0.5 * (k1 + k2));
        }
    }
}

extern "C" void kernel_launch(void* const* d_in, const int* in_sizes, int n_in,
                              void* d_out, int out_size) {
    const float* xyz1    = (const float*)d_in[0];
    const float* xyz2    = (const float*)d_in[1];
    const float* hsv1    = (const float*)d_in[2];
    const float* hsv2    = (const float*)d_in[3];
    const float* normal1 = (const float*)d_in[4];
    const float* normal2 = (const float*)d_in[5];
    const float* nres1   = (const float*)d_in[6];
    const float* nres2   = (const float*)d_in[7];
    const float* R12     = (const float*)d_in[8];
    const float* t12     = (const float*)d_in[9];
    const float* R21     = (const float*)d_in[10];
    const float* t21     = (const float*)d_in[11];
    const int*   npts1   = (const int*)d_in[12];
    const int*   npts2   = (const int*)d_in[13];
    float* out = (float*)d_out;

    init_kernel<<<1, 1024>>>();
    dim3 bgrid(BB * PP / 256, 2);
    count_kernel<<<bgrid, 256>>>(xyz1, xyz2, npts1, npts2);
    scan_kernel<<<4, 1024>>>();
    fill_kernel<<<bgrid, 256>>>(xyz1, xyz2, npts1, npts2);
    dim3 qgrid(BB * PP / NT, 2);
    query_kernel<<<qgrid, NT>>>(xyz1, hsv1, normal1, nres1,
                                xyz2, hsv2, normal2, nres2,
                                R12, t12, R21, t21, npts1, npts2, out);
}

// round 6
// speedup vs baseline: 9.7641x; 9.7641x over previous
#include <cuda_runtime.h>
#include <math.h>

#define BB 2
#define PP 8192
#define KK 20
#define NT 128
#define TILE 256
#define CAP 24

// Fine count grid (threshold oracle only): 1.5 m cells over [-10,10]^2 x [1,61]
#define G2X 14
#define G2Y 14
#define G2Z 40
#define NC2 (G2X * G2Y * G2Z)
#define C2 1.5f
#define INVC2 (1.0f / 1.5f)
#define OXC (-10.0f)
#define OYC (-10.0f)
#define OZC (1.0f)

__device__ double g_acc[2];
__device__ unsigned g_done;
__device__ int g_cnt2[4 * NC2];

__device__ __forceinline__ void cell2_coords(float x, float y, float z,
                                             int& ix, int& iy, int& iz) {
    ix = min(G2X - 1, max(0, (int)floorf((x - OXC) * INVC2)));
    iy = min(G2Y - 1, max(0, (int)floorf((y - OYC) * INVC2)));
    iz = min(G2Z - 1, max(0, (int)floorf((z - OZC) * INVC2)));
}

__global__ void init_kernel() {
    int i = blockIdx.x * blockDim.x + threadIdx.x;
    if (i == 0) { g_acc[0] = 0.0; g_acc[1] = 0.0; g_done = 0u; }
    if (i < 4 * NC2) g_cnt2[i] = 0;
}

// Count valid db points per fine cell, per (side,batch).
__global__ void count2_kernel(const float* __restrict__ xyz1, const float* __restrict__ xyz2,
                              const int* __restrict__ npts1, const int* __restrict__ npts2) {
    const int s = blockIdx.y;
    const int gi = blockIdx.x * blockDim.x + threadIdx.x;
    const int b = gi >> 13;
    const int i = gi & (PP - 1);
    const float* src = s ? xyz1 : xyz2;       // db of side s
    const int ldb = (s ? npts1 : npts2)[b];
    if (i >= ldb) return;
    int g3 = 3 * gi;
    int ix, iy, iz;
    cell2_coords(src[g3], src[g3 + 1], src[g3 + 2], ix, iy, iz);
    atomicAdd(&g_cnt2[(s * BB + b) * NC2 + (iz * G2Y + iy) * G2X + ix], 1);
}

// Brute scan with smem-staged rotated db tiles; preset threshold from cell counts;
// buffered-sieve top-20 (4 sorted chains of 5, packed d2|idx keys); exact epilogue.
__global__ __launch_bounds__(NT) void query_kernel(
    const float* __restrict__ xyz1, const float* __restrict__ hsv1,
    const float* __restrict__ normal1, const float* __restrict__ nres1,
    const float* __restrict__ xyz2, const float* __restrict__ hsv2,
    const float* __restrict__ normal2, const float* __restrict__ nres2,
    const float* __restrict__ R12, const float* __restrict__ t12,
    const float* __restrict__ R21, const float* __restrict__ t21,
    const int* __restrict__ npts1, const int* __restrict__ npts2,
    float* __restrict__ out)
{
    const int s = blockIdx.y;
    const int tid = threadIdx.x;
    const int qi = blockIdx.x * NT + tid;      // batch uniform per block
    const int b = qi >> 13;
    const int p_local = qi & (PP - 1);
    const int boff = b * PP;
    const int set = s * BB + b;

    const float* xq   = s ? xyz2 : xyz1;
    const float* hq   = s ? hsv2 : hsv1;
    const float* nq   = s ? normal2 : normal1;
    const float* rq   = s ? nres2 : nres1;
    const float* xdbr = s ? xyz1 : xyz2;       // raw db points
    const float* ndbr = s ? normal1 : normal2;
    const float* hdb  = s ? hsv1 : hsv2;
    const float* rdb  = s ? nres1 : nres2;
    const float* Rm   = (s ? R21 : R12) + b * 9;
    const float* tv   = (s ? t21 : t12) + b * 3;
    const int lq  = (s ? npts2 : npts1)[b];
    const int ldb = (s ? npts1 : npts2)[b];
    const bool valid = (p_local < lq);

    const float R0 = Rm[0], R1 = Rm[1], R2 = Rm[2];
    const float R3 = Rm[3], R4 = Rm[4], R5 = Rm[5];
    const float R6 = Rm[6], R7 = Rm[7], R8 = Rm[8];
    const float t0 = tv[0], t1 = tv[1], t2 = tv[2];

    // Query mapped into raw db frame: q' = R^T (q - t); |q'-p| == |q - (Rp+t)|.
    const float qx = xq[3 * qi + 0];
    const float qy = xq[3 * qi + 1];
    const float qz = xq[3 * qi + 2];
    const float ux = qx - t0, uy = qy - t1, uz = qz - t2;
    const float qpx = fmaf(R0, ux, fmaf(R3, uy, R6 * uz));
    const float qpy = fmaf(R1, ux, fmaf(R4, uy, R7 * uz));
    const float qpz = fmaf(R2, ux, fmaf(R5, uy, R8 * uz));

    // Preset threshold: expand cube in fine count grid until >= KK points,
    // T^2 = squared distance to farthest corner of the (clamped) cube.
    float thr = 3.0e38f;
    if (valid) {
        int cx, cy, cz;
        cell2_coords(qpx, qpy, qpz, cx, cy, cz);
        const int* cnt2 = g_cnt2 + set * NC2;
        for (int m = 1; m <= 3; m++) {
            int xlo = max(cx - m, 0), xhi = min(cx + m, G2X - 1);
            int ylo = max(cy - m, 0), yhi = min(cy + m, G2Y - 1);
            int zlo = max(cz - m, 0), zhi = min(cz + m, G2Z - 1);
            int cnt = 0;
            for (int z = zlo; z <= zhi; z++)
                for (int y = ylo; y <= yhi; y++) {
                    int rb = (z * G2Y + y) * G2X;
                    for (int x = xlo; x <= xhi; x++) cnt += cnt2[rb + x];
                }
            if (cnt >= KK) {
                float lx = OXC + (float)xlo * C2, hx2 = OXC + (float)(xhi + 1) * C2;
                float ly = OYC + (float)ylo * C2, hy2 = OYC + (float)(yhi + 1) * C2;
                float lz = OZC + (float)zlo * C2, hz2 = OZC + (float)(zhi + 1) * C2;
                float ax = fmaxf(fabsf(qpx - lx), fabsf(qpx - hx2));
                float ay = fmaxf(fabsf(qpy - ly), fabsf(qpy - hy2));
                float az = fmaxf(fabsf(qpz - lz), fabsf(qpz - hz2));
                thr = fmaf(ax, ax, fmaf(ay, ay, az * az)) * 1.0005f;
                break;
            }
        }
    } else {
        thr = -1.0f;   // invalid query: never accept anything
    }

    float keys[KK];    // 4 sorted-ascending chains of 5: tails at 4,9,14,19
#pragma unroll
    for (int k = 0; k < KK; k++) keys[k] = 3.0e38f;
    const float T2cap = thr;
    int cnt = 0;

    __shared__ float4 sm[TILE];
    __shared__ unsigned buf[CAP][NT];

    // Insert all buffered keys into the chains, tighten threshold.
    auto flushf = [&]() {
        for (int j2 = 0; j2 < cnt; j2++) {
            float x = __uint_as_float(buf[j2][tid]);
            float tt0 = keys[4], tt1 = keys[9], tt2 = keys[14], tt3 = keys[19];
            int sel = 0; float bestv = tt0;
            if (tt1 > bestv) { bestv = tt1; sel = 1; }
            if (tt2 > bestv) { bestv = tt2; sel = 2; }
            if (tt3 > bestv) { bestv = tt3; sel = 3; }
            float x0 = (sel == 0) ? x : 3.3e38f;
            float x1 = (sel == 1) ? x : 3.3e38f;
            float x2 = (sel == 2) ? x : 3.3e38f;
            float x3 = (sel == 3) ? x : 3.3e38f;
#pragma unroll
            for (int k = 0; k < 5; k++) {
                float lo = fminf(x0, keys[k]); x0 = fmaxf(x0, keys[k]); keys[k] = lo;
            }
#pragma unroll
            for (int k = 5; k < 10; k++) {
                float lo = fminf(x1, keys[k]); x1 = fmaxf(x1, keys[k]); keys[k] = lo;
            }
#pragma unroll
            for (int k = 10; k < 15; k++) {
                float lo = fminf(x2, keys[k]); x2 = fmaxf(x2, keys[k]); keys[k] = lo;
            }
#pragma unroll
            for (int k = 15; k < 20; k++) {
                float lo = fminf(x3, keys[k]); x3 = fmaxf(x3, keys[k]); keys[k] = lo;
            }
        }
        cnt = 0;
        float tail = fmaxf(fmaxf(keys[4], keys[9]), fmaxf(keys[14], keys[19]));
        if (valid) thr = fminf(T2cap, tail * 1.001f);
    };

    const int ntile = (ldb + TILE - 1) / TILE;
    for (int tb = 0; tb < ntile; ++tb) {
        const int base = tb * TILE;
        __syncthreads();
        // Stage TILE raw db points rotated into query-side frame? No — scan runs in
        // RAW frame (q' trick), so staging is a plain copy of raw points.
#pragma unroll
        for (int c = 0; c < TILE / NT; c++) {
            int e = c * NT + tid;
            int j = base + e;
            float4 v;
            if (j < ldb) {
                int g3 = 3 * (boff + j);
                v = make_float4(xdbr[g3 + 0], xdbr[g3 + 1], xdbr[g3 + 2], 0.f);
            } else {
                v = make_float4(1e30f, 1e30f, 1e30f, 0.f);
            }
            sm[e] = v;
        }
        __syncthreads();

        if (thr > 0.0f) {   // warp-coherent: invalid warps skip compute
            for (int jj = 0; jj < TILE; jj += 8) {
                float d2a[8];
#pragma unroll
                for (int u = 0; u < 8; u++) {
                    float4 pv = sm[jj + u];
                    float dx = qpx - pv.x, dy = qpy - pv.y, dz = qpz - pv.z;
                    d2a[u] = fmaf(dx, dx, fmaf(dy, dy, dz * dz));
                }
                float m8 = fminf(fminf(fminf(d2a[0], d2a[1]), fminf(d2a[2], d2a[3])),
                                 fminf(fminf(d2a[4], d2a[5]), fminf(d2a[6], d2a[7])));
                if (m8 < thr) {
#pragma unroll
                    for (int u = 0; u < 8; u++) {
                        if (d2a[u] < thr) {
                            buf[cnt][tid] = (__float_as_uint(d2a[u]) & 0xFFFFE000u)
                                          | (unsigned)(base + jj + u);
                            if (++cnt == CAP) flushf();
                        }
                    }
                }
            }
        }
        // Per-tile flush (cheap skip if whole warp empty).
        if (__ballot_sync(0xffffffffu, cnt > 0)) flushf();
    }
    if (cnt > 0) flushf();

    // Exact epilogue over the 20 winners (raw-frame distances; query normal rotated by R^T).
    float sum = 0.f;
    if (valid) {
        float ell = fmaxf(0.015f * (qz - 10.0f), 0.15f);
        float inv_ls = 1.0f / (ell * ell);
        float hx = hq[3 * qi + 0], hy = hq[3 * qi + 1], hz = hq[3 * qi + 2];
        float nxr = nq[3 * qi + 0], nyr = nq[3 * qi + 1], nzr = nq[3 * qi + 2];
        float npx = fmaf(R0, nxr, fmaf(R3, nyr, R6 * nzr));
        float npy = fmaf(R1, nxr, fmaf(R4, nyr, R7 * nzr));
        float npz = fmaf(R2, nxr, fmaf(R5, nyr, R8 * nzr));
        float rqv = rq[qi];
#pragma unroll
        for (int k = 0; k < KK; k++) {
            int idx = (int)(__float_as_uint(keys[k]) & 0x1FFFu);
            int g3 = 3 * (boff + idx);
            float dx = qpx - xdbr[g3 + 0];
            float dy = qpy - xdbr[g3 + 1];
            float dz = qpz - xdbr[g3 + 2];
            float d2 = fmaf(dx, dx, fmaf(dy, dy, dz * dz));
            float ndot = fmaf(npx, ndbr[g3 + 0], fmaf(npy, ndbr[g3 + 1], npz * ndbr[g3 + 2]));
            float chx = hx - hdb[g3 + 0];
            float chy = hy - hdb[g3 + 1];
            float chz = hz - hdb[g3 + 2];
            float cd = sqrtf(fmaf(chx, chx, fmaf(chy, chy, chz * chz)) + 1e-12f);
            float rk = rdb[boff + idx];
            float alpha = 0.2f / (0.1f + rqv + rk);
            float nk = fmaxf(ndot * alpha, 0.0f);
            sum += __expf(-(d2 * inv_ls + cd * 5.0f)) * nk;
        }
    }

    // Warp + block reduce, one double atomic per block; last block finalizes.
#pragma unroll
    for (int o = 16; o > 0; o >>= 1) sum += __shfl_down_sync(0xffffffffu, sum, o);
    __shared__ float wsum[NT / 32];
    if ((tid & 31) == 0) wsum[tid >> 5] = sum;
    __syncthreads();
    if (tid == 0) {
        float bs = 0.f;
#pragma unroll
        for (int w = 0; w < NT / 32; w++) bs += wsum[w];
        atomicAdd(&g_acc[s], (double)bs);
        __threadfence();
        unsigned done = atomicAdd(&g_done, 1u);
        if (done == (unsigned)(gridDim.x * gridDim.y) - 1u) {
            double s1 = (double)npts1[0] + (double)npts1[1];
            double s2 = (double)npts2[0] + (double)npts2[1];
            double k1 = g_acc[0] / (s1 * (double)KK);
            double k2 = g_acc[1] / (s2 * (double)KK);
            out[0] = (float)(0.5 * (k1 + k2));
        }
    }
}

extern "C" void kernel_launch(void* const* d_in, const int* in_sizes, int n_in,
                              void* d_out, int out_size) {
    const float* xyz1    = (const float*)d_in[0];
    const float* xyz2    = (const float*)d_in[1];
    const float* hsv1    = (const float*)d_in[2];
    const float* hsv2    = (const float*)d_in[3];
    const float* normal1 = (const float*)d_in[4];
    const float* normal2 = (const float*)d_in[5];
    const float* nres1   = (const float*)d_in[6];
    const float* nres2   = (const float*)d_in[7];
    const float* R12     = (const float*)d_in[8];
    const float* t12     = (const float*)d_in[9];
    const float* R21     = (const float*)d_in[10];
    const float* t21     = (const float*)d_in[11];
    const int*   npts1   = (const int*)d_in[12];
    const int*   npts2   = (const int*)d_in[13];
    float* out = (float*)d_out;

    init_kernel<<<(4 * NC2 + 1023) / 1024, 1024>>>();
    dim3 bgrid(BB * PP / 256, 2);
    count2_kernel<<<bgrid, 256>>>(xyz1, xyz2, npts1, npts2);
    dim3 qgrid(BB * PP / NT, 2);
    query_kernel<<<qgrid, NT>>>(xyz1, hsv1, normal1, nres1,
                                xyz2, hsv2, normal2, nres2,
                                R12, t12, R21, t21, npts1, npts2, out);
}

// round 7
// speedup vs baseline: 11.8462x; 1.2132x over previous
#include <cuda_runtime.h>
#include <math.h>

#define BB 2
#define PP 8192
#define KK 20
#define QB 32          // queries per block (one per lane)
#define NW 4           // db shards = warps per block

// Fine count grid (threshold oracle only): 1.5 m cells over [-10,10]^2 x [1,61]
#define G2X 14
#define G2Y 14
#define G2Z 40
#define NC2 (G2X * G2Y * G2Z)
#define C2 1.5f
#define INVC2 (1.0f / 1.5f)
#define OXC (-10.0f)
#define OYC (-10.0f)
#define OZC (1.0f)

__device__ double g_acc[2];
__device__ unsigned g_done;
__device__ int g_cnt2[4 * NC2];

__device__ __forceinline__ void cell2_coords(float x, float y, float z,
                                             int& ix, int& iy, int& iz) {
    ix = min(G2X - 1, max(0, (int)floorf((x - OXC) * INVC2)));
    iy = min(G2Y - 1, max(0, (int)floorf((y - OYC) * INVC2)));
    iz = min(G2Z - 1, max(0, (int)floorf((z - OZC) * INVC2)));
}

__global__ void init_kernel() {
    int i = blockIdx.x * blockDim.x + threadIdx.x;
    if (i == 0) { g_acc[0] = 0.0; g_acc[1] = 0.0; g_done = 0u; }
    if (i < 4 * NC2) g_cnt2[i] = 0;
}

__global__ void count2_kernel(const float* __restrict__ xyz1, const float* __restrict__ xyz2,
                              const int* __restrict__ npts1, const int* __restrict__ npts2) {
    const int s = blockIdx.y;
    const int gi = blockIdx.x * blockDim.x + threadIdx.x;
    const int b = gi >> 13;
    const int i = gi & (PP - 1);
    const float* src = s ? xyz1 : xyz2;       // db of side s
    const int ldb = (s ? npts1 : npts2)[b];
    if (i >= ldb) return;
    int g3 = 3 * gi;
    int ix, iy, iz;
    cell2_coords(src[g3], src[g3 + 1], src[g3 + 2], ix, iy, iz);
    atomicAdd(&g_cnt2[(s * BB + b) * NC2 + (iz * G2Y + iy) * G2X + ix], 1);
}

// Block = 32 queries x 4 db-shard warps. Each warp scans its quarter of the db
// (|p|^2-2q.p form, per-warp smem tiles), keeps its own top-20 as 4 sorted chains
// of 5 packed keys; shards merge via smem; warp 0 does the exact epilogue.
__global__ __launch_bounds__(QB * NW) void query_kernel(
    const float* __restrict__ xyz1, const float* __restrict__ hsv1,
    const float* __restrict__ normal1, const float* __restrict__ nres1,
    const float* __restrict__ xyz2, const float* __restrict__ hsv2,
    const float* __restrict__ normal2, const float* __restrict__ nres2,
    const float* __restrict__ R12, const float* __restrict__ t12,
    const float* __restrict__ R21, const float* __restrict__ t21,
    const int* __restrict__ npts1, const int* __restrict__ npts2,
    float* __restrict__ out)
{
    const int s = blockIdx.y;
    const int lane = threadIdx.x & 31;
    const int w = threadIdx.x >> 5;
    const int qi = blockIdx.x * QB + lane;    // same 32 queries for all 4 warps
    const int b = qi >> 13;
    const int p_local = qi & (PP - 1);
    const int boff = b * PP;
    const int set = s * BB + b;

    const float* xq   = s ? xyz2 : xyz1;
    const float* hq   = s ? hsv2 : hsv1;
    const float* nq   = s ? normal2 : normal1;
    const float* rq   = s ? nres2 : nres1;
    const float* xdbr = s ? xyz1 : xyz2;      // raw db points
    const float* ndbr = s ? normal1 : normal2;
    const float* hdb  = s ? hsv1 : hsv2;
    const float* rdb  = s ? nres1 : nres2;
    const float* Rm   = (s ? R21 : R12) + b * 9;
    const float* tv   = (s ? t21 : t12) + b * 3;
    const int lq  = (s ? npts2 : npts1)[b];
    const int ldb = (s ? npts1 : npts2)[b];
    const bool valid = (p_local < lq);

    const float R0 = Rm[0], R1 = Rm[1], R2 = Rm[2];
    const float R3 = Rm[3], R4 = Rm[4], R5 = Rm[5];
    const float R6 = Rm[6], R7 = Rm[7], R8 = Rm[8];

    // q' = R^T (q - t): distance-equivalent query in raw db frame.
    const float qx = xq[3 * qi + 0];
    const float qy = xq[3 * qi + 1];
    const float qz = xq[3 * qi + 2];
    const float ux = qx - tv[0], uy = qy - tv[1], uz = qz - tv[2];
    const float qpx = fmaf(R0, ux, fmaf(R3, uy, R6 * uz));
    const float qpy = fmaf(R1, ux, fmaf(R4, uy, R7 * uz));
    const float qpz = fmaf(R2, ux, fmaf(R5, uy, R8 * uz));
    const float q2 = fmaf(qpx, qpx, fmaf(qpy, qpy, qpz * qpz));
    const float m2x = -2.f * qpx, m2y = -2.f * qpy, m2z = -2.f * qpz;

    __shared__ float4 tile[NW][64];
    __shared__ float sthr[QB];
    __shared__ float skeys[NW - 1][QB][KK + 1];   // +1 pad: conflict-free

    // Preset threshold via count grid (warp 0 computes, all warps share).
    if (w == 0) {
        float T2 = -1.0f;
        if (valid) {
            int cx, cy, cz;
            cell2_coords(qpx, qpy, qpz, cx, cy, cz);
            const int* cnt2 = g_cnt2 + set * NC2;
            for (int m = 1; m <= 3; m++) {
                int xlo = max(cx - m, 0), xhi = min(cx + m, G2X - 1);
                int ylo = max(cy - m, 0), yhi = min(cy + m, G2Y - 1);
                int zlo = max(cz - m, 0), zhi = min(cz + m, G2Z - 1);
                int cnt = 0;
                for (int z = zlo; z <= zhi; z++)
                    for (int y = ylo; y <= yhi; y++) {
                        int rb = (z * G2Y + y) * G2X;
                        for (int x = xlo; x <= xhi; x++) cnt += cnt2[rb + x];
                    }
                if (cnt >= KK) {
                    float lx = OXC + (float)xlo * C2, hx2 = OXC + (float)(xhi + 1) * C2;
                    float ly = OYC + (float)ylo * C2, hy2 = OYC + (float)(yhi + 1) * C2;
                    float lz = OZC + (float)zlo * C2, hz2 = OZC + (float)(zhi + 1) * C2;
                    float ax = fmaxf(fabsf(qpx - lx), fabsf(qpx - hx2));
                    float ay = fmaxf(fabsf(qpy - ly), fabsf(qpy - hy2));
                    float az = fmaxf(fabsf(qpz - lz), fabsf(qpz - hz2));
                    T2 = fmaf(ax, ax, fmaf(ay, ay, az * az)) * 1.002f;
                    break;
                }
            }
        }
        sthr[lane] = T2;
    }
    __syncthreads();

    float thr = sthr[lane];                   // -1 for invalid queries
    const float T2cap = thr;
    float thrp = (thr > 0.f) ? thr - q2 : -3.0e38f;   // shifted-space threshold

    float keys[KK];                           // 4 chains of 5: tails at 4,9,14,19
#pragma unroll
    for (int k = 0; k < KK; k++) keys[k] = 3.0e38f;

    const bool active = __ballot_sync(0xffffffffu, thr > 0.f) != 0u;
    const int j0 = (ldb * w) >> 2;
    const int j1 = (ldb * (w + 1)) >> 2;

    if (active) {
        for (int base = j0; base < j1; base += 64) {
            __syncwarp();
#pragma unroll
            for (int c = 0; c < 2; c++) {
                int j = base + c * 32 + lane;
                float4 v;
                if (j < j1) {
                    int g3 = 3 * (boff + j);
                    float px = xdbr[g3 + 0], py = xdbr[g3 + 1], pz = xdbr[g3 + 2];
                    v = make_float4(px, py, pz, fmaf(px, px, fmaf(py, py, pz * pz)));
                } else {
                    v = make_float4(0.f, 0.f, 0.f, 3.0e38f);  // d2' huge -> rejected
                }
                tile[w][c * 32 + lane] = v;
            }
            __syncwarp();

            for (int jj = 0; jj < 64; jj += 8) {
                float d2a[8];
#pragma unroll
                for (int u = 0; u < 8; u++) {
                    float4 pv = tile[w][jj + u];
                    d2a[u] = fmaf(m2x, pv.x, fmaf(m2y, pv.y, fmaf(m2z, pv.z, pv.w)));
                }
                float m8 = fminf(fminf(fminf(d2a[0], d2a[1]), fminf(d2a[2], d2a[3])),
                                 fminf(fminf(d2a[4], d2a[5]), fminf(d2a[6], d2a[7])));
                if (m8 < thrp) {
#pragma unroll
                    for (int u = 0; u < 8; u++) {
                        if (d2a[u] < thrp) {
                            float d2 = d2a[u] + q2;          // true d2 (>=0)
                            float x = __uint_as_float(
                                (__float_as_uint(d2) & 0xFFFFE000u)
                                | (unsigned)(base + jj + u));
                            float tt0 = keys[4], tt1 = keys[9], tt2 = keys[14], tt3 = keys[19];
                            int sel = 0; float bestv = tt0;
                            if (tt1 > bestv) { bestv = tt1; sel = 1; }
                            if (tt2 > bestv) { bestv = tt2; sel = 2; }
                            if (tt3 > bestv) { bestv = tt3; sel = 3; }
                            float x0 = (sel == 0) ? x : 3.3e38f;
                            float x1 = (sel == 1) ? x : 3.3e38f;
                            float x2 = (sel == 2) ? x : 3.3e38f;
                            float x3 = (sel == 3) ? x : 3.3e38f;
#pragma unroll
                            for (int k = 0; k < 5; k++) {
                                float lo = fminf(x0, keys[k]); x0 = fmaxf(x0, keys[k]); keys[k] = lo;
                            }
#pragma unroll
                            for (int k = 5; k < 10; k++) {
                                float lo = fminf(x1, keys[k]); x1 = fmaxf(x1, keys[k]); keys[k] = lo;
                            }
#pragma unroll
                            for (int k = 10; k < 15; k++) {
                                float lo = fminf(x2, keys[k]); x2 = fmaxf(x2, keys[k]); keys[k] = lo;
                            }
#pragma unroll
                            for (int k = 15; k < 20; k++) {
                                float lo = fminf(x3, keys[k]); x3 = fmaxf(x3, keys[k]); keys[k] = lo;
                            }
                            float tail = fmaxf(fmaxf(keys[4], keys[9]),
                                               fmaxf(keys[14], keys[19]));
                            thr = fminf(T2cap, tail * 1.002f);
                            thrp = thr - q2;
                        }
                    }
                }
            }
        }
    }

    // Shard merge: warps 1..3 publish chains; warp 0 folds them in.
    if (w > 0) {
#pragma unroll
        for (int k = 0; k < KK; k++) skeys[w - 1][lane][k] = keys[k];
    }
    __syncthreads();

    if (w == 0) {
        float tail = fmaxf(fmaxf(keys[4], keys[9]), fmaxf(keys[14], keys[19]));
#pragma unroll
        for (int ws = 0; ws < NW - 1; ws++) {
#pragma unroll
            for (int k = 0; k < KK; k++) {
                float x = skeys[ws][lane][k];
                if (x < tail) {
                    float tt0 = keys[4], tt1 = keys[9], tt2 = keys[14], tt3 = keys[19];
                    int sel = 0; float bestv = tt0;
                    if (tt1 > bestv) { bestv = tt1; sel = 1; }
                    if (tt2 > bestv) { bestv = tt2; sel = 2; }
                    if (tt3 > bestv) { bestv = tt3; sel = 3; }
                    float x0 = (sel == 0) ? x : 3.3e38f;
                    float x1 = (sel == 1) ? x : 3.3e38f;
                    float x2 = (sel == 2) ? x : 3.3e38f;
                    float x3 = (sel == 3) ? x : 3.3e38f;
#pragma unroll
                    for (int k2 = 0; k2 < 5; k2++) {
                        float lo = fminf(x0, keys[k2]); x0 = fmaxf(x0, keys[k2]); keys[k2] = lo;
                    }
#pragma unroll
                    for (int k2 = 5; k2 < 10; k2++) {
                        float lo = fminf(x1, keys[k2]); x1 = fmaxf(x1, keys[k2]); keys[k2] = lo;
                    }
#pragma unroll
                    for (int k2 = 10; k2 < 15; k2++) {
                        float lo = fminf(x2, keys[k2]); x2 = fmaxf(x2, keys[k2]); keys[k2] = lo;
                    }
#pragma unroll
                    for (int k2 = 15; k2 < 20; k2++) {
                        float lo = fminf(x3, keys[k2]); x3 = fmaxf(x3, keys[k2]); keys[k2] = lo;
                    }
                    tail = fmaxf(fmaxf(keys[4], keys[9]), fmaxf(keys[14], keys[19]));
                }
            }
        }

        // Exact epilogue over the merged 20 winners.
        float sum = 0.f;
        if (valid) {
            float ell = fmaxf(0.015f * (qz - 10.0f), 0.15f);
            float inv_ls = 1.0f / (ell * ell);
            float hx = hq[3 * qi + 0], hy = hq[3 * qi + 1], hz = hq[3 * qi + 2];
            float nxr = nq[3 * qi + 0], nyr = nq[3 * qi + 1], nzr = nq[3 * qi + 2];
            float npx = fmaf(R0, nxr, fmaf(R3, nyr, R6 * nzr));
            float npy = fmaf(R1, nxr, fmaf(R4, nyr, R7 * nzr));
            float npz = fmaf(R2, nxr, fmaf(R5, nyr, R8 * nzr));
            float rqv = rq[qi];
#pragma unroll
            for (int k = 0; k < KK; k++) {
                int idx = (int)(__float_as_uint(keys[k]) & 0x1FFFu);
                int g3 = 3 * (boff + idx);
                float dx = qpx - xdbr[g3 + 0];
                float dy = qpy - xdbr[g3 + 1];
                float dz = qpz - xdbr[g3 + 2];
                float d2 = fmaf(dx, dx, fmaf(dy, dy, dz * dz));
                float ndot = fmaf(npx, ndbr[g3 + 0],
                                  fmaf(npy, ndbr[g3 + 1], npz * ndbr[g3 + 2]));
                float chx = hx - hdb[g3 + 0];
                float chy = hy - hdb[g3 + 1];
                float chz = hz - hdb[g3 + 2];
                float cd = sqrtf(fmaf(chx, chx, fmaf(chy, chy, chz * chz)) + 1e-12f);
                float rk = rdb[boff + idx];
                float alpha = 0.2f / (0.1f + rqv + rk);
                float nk = fmaxf(ndot * alpha, 0.0f);
                sum += __expf(-(d2 * inv_ls + cd * 5.0f)) * nk;
            }
        }

        // Warp reduce + one double atomic per block; last block finalizes.
#pragma unroll
        for (int o = 16; o > 0; o >>= 1) sum += __shfl_down_sync(0xffffffffu, sum, o);
        if (lane == 0) {
            atomicAdd(&g_acc[s], (double)sum);
            __threadfence();
            unsigned done = atomicAdd(&g_done, 1u);
            if (done == (unsigned)(gridDim.x * gridDim.y) - 1u) {
                double s1 = (double)npts1[0] + (double)npts1[1];
                double s2 = (double)npts2[0] + (double)npts2[1];
                double k1 = g_acc[0] / (s1 * (double)KK);
                double k2 = g_acc[1] / (s2 * (double)KK);
                out[0] = (float)(0.5 * (k1 + k2));
            }
        }
    }
}

extern "C" void kernel_launch(void* const* d_in, const int* in_sizes, int n_in,
                              void* d_out, int out_size) {
    const float* xyz1    = (const float*)d_in[0];
    const float* xyz2    = (const float*)d_in[1];
    const float* hsv1    = (const float*)d_in[2];
    const float* hsv2    = (const float*)d_in[3];
    const float* normal1 = (const float*)d_in[4];
    const float* normal2 = (const float*)d_in[5];
    const float* nres1   = (const float*)d_in[6];
    const float* nres2   = (const float*)d_in[7];
    const float* R12     = (const float*)d_in[8];
    const float* t12     = (const float*)d_in[9];
    const float* R21     = (const float*)d_in[10];
    const float* t21     = (const float*)d_in[11];
    const int*   npts1   = (const int*)d_in[12];
    const int*   npts2   = (const int*)d_in[13];
    float* out = (float*)d_out;

    init_kernel<<<(4 * NC2 + 1023) / 1024, 1024>>>();
    dim3 bgrid(BB * PP / 256, 2);
    count2_kernel<<<bgrid, 256>>>(xyz1, xyz2, npts1, npts2);
    dim3 qgrid(BB * PP / QB, 2);
    query_kernel<<<qgrid, QB * NW>>>(xyz1, hsv1, normal1, nres1,
                                     xyz2, hsv2, normal2, nres2,
                                     R12, t12, R21, t21, npts1, npts2, out);
}

// round 8
// speedup vs baseline: 13.5205x; 1.1413x over previous
#include <cuda_runtime.h>
#include <math.h>

#define BB 2
#define PP 8192
#define KK 20
#define QB 32          // queries per block (one per lane)
#define NW 4           // db shards = warps per block
#define TS 128         // tile size (points per shard-tile)

// Fine count grid (threshold oracle only): 1.5 m cells over [-10,10]^2 x [1,61]
#define G2X 14
#define G2Y 14
#define G2Z 40
#define NC2 (G2X * G2Y * G2Z)
#define C2 1.5f
#define INVC2 (1.0f / 1.5f)
#define OXC (-10.0f)
#define OYC (-10.0f)
#define OZC (1.0f)

__device__ double g_acc[2];
__device__ unsigned g_done;
__device__ int g_cnt2[4 * NC2];

__device__ __forceinline__ void cell2_coords(float x, float y, float z,
                                             int& ix, int& iy, int& iz) {
    ix = min(G2X - 1, max(0, (int)floorf((x - OXC) * INVC2)));
    iy = min(G2Y - 1, max(0, (int)floorf((y - OYC) * INVC2)));
    iz = min(G2Z - 1, max(0, (int)floorf((z - OZC) * INVC2)));
}

__global__ void init_kernel() {
    int i = blockIdx.x * blockDim.x + threadIdx.x;
    if (i == 0) { g_acc[0] = 0.0; g_acc[1] = 0.0; g_done = 0u; }
    if (i < 4 * NC2) g_cnt2[i] = 0;
}

__global__ void count2_kernel(const float* __restrict__ xyz1, const float* __restrict__ xyz2,
                              const int* __restrict__ npts1, const int* __restrict__ npts2) {
    const int s = blockIdx.y;
    const int gi = blockIdx.x * blockDim.x + threadIdx.x;
    const int b = gi >> 13;
    const int i = gi & (PP - 1);
    const float* src = s ? xyz1 : xyz2;       // db of side s
    const int ldb = (s ? npts1 : npts2)[b];
    if (i >= ldb) return;
    int g3 = 3 * gi;
    int ix, iy, iz;
    cell2_coords(src[g3], src[g3 + 1], src[g3 + 2], ix, iy, iz);
    atomicAdd(&g_cnt2[(s * BB + b) * NC2 + (iz * G2Y + iy) * G2X + ix], 1);
}

// Insert packed key x into 4 sorted chains of 5 (tails at 4,9,14,19).
#define CHAIN_INSERT(keys, x)                                                   \
    do {                                                                        \
        float tt0 = keys[4], tt1 = keys[9], tt2 = keys[14], tt3 = keys[19];     \
        int sel_ = 0; float bv_ = tt0;                                          \
        if (tt1 > bv_) { bv_ = tt1; sel_ = 1; }                                 \
        if (tt2 > bv_) { bv_ = tt2; sel_ = 2; }                                 \
        if (tt3 > bv_) { bv_ = tt3; sel_ = 3; }                                 \
        float x0_ = (sel_ == 0) ? (x) : 3.3e38f;                                \
        float x1_ = (sel_ == 1) ? (x) : 3.3e38f;                                \
        float x2_ = (sel_ == 2) ? (x) : 3.3e38f;                                \
        float x3_ = (sel_ == 3) ? (x) : 3.3e38f;                                \
        _Pragma("unroll")                                                       \
        for (int k_ = 0; k_ < 5; k_++) {                                        \
            float lo_ = fminf(x0_, keys[k_]); x0_ = fmaxf(x0_, keys[k_]); keys[k_] = lo_; } \
        _Pragma("unroll")                                                       \
        for (int k_ = 5; k_ < 10; k_++) {                                       \
            float lo_ = fminf(x1_, keys[k_]); x1_ = fmaxf(x1_, keys[k_]); keys[k_] = lo_; } \
        _Pragma("unroll")                                                       \
        for (int k_ = 10; k_ < 15; k_++) {                                      \
            float lo_ = fminf(x2_, keys[k_]); x2_ = fmaxf(x2_, keys[k_]); keys[k_] = lo_; } \
        _Pragma("unroll")                                                       \
        for (int k_ = 15; k_ < 20; k_++) {                                      \
            float lo_ = fminf(x3_, keys[k_]); x3_ = fmaxf(x3_, keys[k_]); keys[k_] = lo_; } \
    } while (0)

// Block = 32 queries x 4 db-shard warps; mid-scan merges tighten the shared threshold.
__global__ __launch_bounds__(QB * NW) void query_kernel(
    const float* __restrict__ xyz1, const float* __restrict__ hsv1,
    const float* __restrict__ normal1, const float* __restrict__ nres1,
    const float* __restrict__ xyz2, const float* __restrict__ hsv2,
    const float* __restrict__ normal2, const float* __restrict__ nres2,
    const float* __restrict__ R12, const float* __restrict__ t12,
    const float* __restrict__ R21, const float* __restrict__ t21,
    const int* __restrict__ npts1, const int* __restrict__ npts2,
    float* __restrict__ out)
{
    const int s = blockIdx.y;
    const int lane = threadIdx.x & 31;
    const int w = threadIdx.x >> 5;
    const int qi = blockIdx.x * QB + lane;    // same 32 queries for all 4 warps
    const int b = qi >> 13;
    const int p_local = qi & (PP - 1);
    const int boff = b * PP;
    const int set = s * BB + b;

    const float* xq   = s ? xyz2 : xyz1;
    const float* hq   = s ? hsv2 : hsv1;
    const float* nq   = s ? normal2 : normal1;
    const float* rq   = s ? nres2 : nres1;
    const float* xdbr = s ? xyz1 : xyz2;      // raw db points
    const float* ndbr = s ? normal1 : normal2;
    const float* hdb  = s ? hsv1 : hsv2;
    const float* rdb  = s ? nres1 : nres2;
    const float* Rm   = (s ? R21 : R12) + b * 9;
    const float* tv   = (s ? t21 : t12) + b * 3;
    const int lq  = (s ? npts2 : npts1)[b];
    const int ldb = (s ? npts1 : npts2)[b];
    const bool valid = (p_local < lq);

    const float R0 = Rm[0], R1 = Rm[1], R2 = Rm[2];
    const float R3 = Rm[3], R4 = Rm[4], R5 = Rm[5];
    const float R6 = Rm[6], R7 = Rm[7], R8 = Rm[8];

    // q' = R^T (q - t): distance-equivalent query in raw db frame.
    const float qx = xq[3 * qi + 0];
    const float qy = xq[3 * qi + 1];
    const float qz = xq[3 * qi + 2];
    const float ux = qx - tv[0], uy = qy - tv[1], uz = qz - tv[2];
    const float qpx = fmaf(R0, ux, fmaf(R3, uy, R6 * uz));
    const float qpy = fmaf(R1, ux, fmaf(R4, uy, R7 * uz));
    const float qpz = fmaf(R2, ux, fmaf(R5, uy, R8 * uz));
    const float q2 = fmaf(qpx, qpx, fmaf(qpy, qpy, qpz * qpz));
    const float m2x = -2.f * qpx, m2y = -2.f * qpy, m2z = -2.f * qpz;

    __shared__ float4 tile[NW][TS];
    __shared__ float sthr[QB];
    __shared__ float skeys[NW - 1][QB][KK + 1];   // +1 pad: conflict-free

    // Preset threshold via count grid (warp 0 computes, all warps share).
    if (w == 0) {
        float T2 = -1.0f;
        if (valid) {
            int cx, cy, cz;
            cell2_coords(qpx, qpy, qpz, cx, cy, cz);
            const int* cnt2 = g_cnt2 + set * NC2;
            for (int m = 1; m <= 3; m++) {
                int xlo = max(cx - m, 0), xhi = min(cx + m, G2X - 1);
                int ylo = max(cy - m, 0), yhi = min(cy + m, G2Y - 1);
                int zlo = max(cz - m, 0), zhi = min(cz + m, G2Z - 1);
                int cnt = 0;
                for (int z = zlo; z <= zhi; z++)
                    for (int y = ylo; y <= yhi; y++) {
                        int rb = (z * G2Y + y) * G2X;
                        for (int x = xlo; x <= xhi; x++) cnt += cnt2[rb + x];
                    }
                if (cnt >= KK) {
                    float lx = OXC + (float)xlo * C2, hx2 = OXC + (float)(xhi + 1) * C2;
                    float ly = OYC + (float)ylo * C2, hy2 = OYC + (float)(yhi + 1) * C2;
                    float lz = OZC + (float)zlo * C2, hz2 = OZC + (float)(zhi + 1) * C2;
                    float ax = fmaxf(fabsf(qpx - lx), fabsf(qpx - hx2));
                    float ay = fmaxf(fabsf(qpy - ly), fabsf(qpy - hy2));
                    float az = fmaxf(fabsf(qpz - lz), fabsf(qpz - hz2));
                    T2 = fmaf(ax, ax, fmaf(ay, ay, az * az)) * 1.002f;
                    break;
                }
            }
        }
        sthr[lane] = T2;
    }
    __syncthreads();

    float thrcap = sthr[lane];                // -1 for invalid queries (never accept)
    float thr = thrcap;
    float thrp = (thr > 0.f) ? thr - q2 : -3.0e38f;   // shifted-space threshold

    float keys[KK];
#pragma unroll
    for (int k = 0; k < KK; k++) keys[k] = 3.0e38f;

    const bool active = __ballot_sync(0xffffffffu, thr > 0.f) != 0u;  // block-uniform
    const int j0 = (ldb * w) >> 2;
    const int j1 = (ldb * (w + 1)) >> 2;
    const int ntile = (((ldb + 3) >> 2) + TS - 1) / TS;   // uniform across warps

    if (active) {
        for (int tb = 0; tb < ntile; ++tb) {
            const int base = j0 + tb * TS;
            __syncwarp();
#pragma unroll
            for (int c = 0; c < TS / 32; c++) {
                int j = base + c * 32 + lane;
                float4 v;
                if (j < j1) {
                    int g3 = 3 * (boff + j);
                    float px = xdbr[g3 + 0], py = xdbr[g3 + 1], pz = xdbr[g3 + 2];
                    v = make_float4(px, py, pz, fmaf(px, px, fmaf(py, py, pz * pz)));
                } else {
                    v = make_float4(0.f, 0.f, 0.f, 3.0e38f);  // d2' huge -> rejected
                }
                tile[w][c * 32 + lane] = v;
            }
            __syncwarp();

            for (int jj = 0; jj < TS; jj += 8) {
                float d2a[8];
#pragma unroll
                for (int u = 0; u < 8; u++) {
                    float4 pv = tile[w][jj + u];
                    d2a[u] = fmaf(m2x, pv.x, fmaf(m2y, pv.y, fmaf(m2z, pv.z, pv.w)));
                }
                float m8 = fminf(fminf(fminf(d2a[0], d2a[1]), fminf(d2a[2], d2a[3])),
                                 fminf(fminf(d2a[4], d2a[5]), fminf(d2a[6], d2a[7])));
                if (m8 < thrp) {
#pragma unroll
                    for (int u = 0; u < 8; u++) {
                        if (d2a[u] < thrp) {
                            float d2 = d2a[u] + q2;          // true d2 (>=0)
                            float x = __uint_as_float(
                                (__float_as_uint(d2) & 0xFFFFE000u)
                                | (unsigned)(base + jj + u));
                            CHAIN_INSERT(keys, x);
                            float tail = fmaxf(fmaxf(keys[4], keys[9]),
                                               fmaxf(keys[14], keys[19]));
                            thr = fminf(thrcap, tail * 1.002f);
                            thrp = thr - q2;
                        }
                    }
                }
            }

            // Mid-scan cross-warp merges: tighten threshold to true top-20-so-far.
            if (tb == 1 || tb == 4) {
                if (w > 0) {
#pragma unroll
                    for (int k = 0; k < KK; k++) skeys[w - 1][lane][k] = keys[k];
                }
                __syncthreads();
                if (w == 0) {
                    float tail = fmaxf(fmaxf(keys[4], keys[9]), fmaxf(keys[14], keys[19]));
#pragma unroll
                    for (int ws = 0; ws < NW - 1; ws++) {
                        for (int k = 0; k < KK; k++) {
                            float x = skeys[ws][lane][k];
                            if (x < tail) {
                                CHAIN_INSERT(keys, x);
                                tail = fmaxf(fmaxf(keys[4], keys[9]),
                                             fmaxf(keys[14], keys[19]));
                            }
                        }
                    }
                    sthr[lane] = fminf(thrcap, tail * 1.002f);
                }
                __syncthreads();
                thrcap = sthr[lane];
                thr = thrcap;
                if (w > 0) {       // candidates now owned by warp 0: reset (no dups)
#pragma unroll
                    for (int k = 0; k < KK; k++) keys[k] = 3.0e38f;
                } else {
                    float tail = fmaxf(fmaxf(keys[4], keys[9]), fmaxf(keys[14], keys[19]));
                    thr = fminf(thrcap, tail * 1.002f);
                }
                thrp = (thr > 0.f) ? thr - q2 : -3.0e38f;
            }
        }
    }

    // Final merge: warps 1..3 publish chains; warp 0 folds them in.
    if (w > 0) {
#pragma unroll
        for (int k = 0; k < KK; k++) skeys[w - 1][lane][k] = keys[k];
    }
    __syncthreads();

    if (w == 0) {
        float tail = fmaxf(fmaxf(keys[4], keys[9]), fmaxf(keys[14], keys[19]));
#pragma unroll
        for (int ws = 0; ws < NW - 1; ws++) {
            for (int k = 0; k < KK; k++) {
                float x = skeys[ws][lane][k];
                if (x < tail) {
                    CHAIN_INSERT(keys, x);
                    tail = fmaxf(fmaxf(keys[4], keys[9]), fmaxf(keys[14], keys[19]));
                }
            }
        }

        // Exact epilogue over the merged 20 winners.
        float sum = 0.f;
        if (valid) {
            float ell = fmaxf(0.015f * (qz - 10.0f), 0.15f);
            float inv_ls = 1.0f / (ell * ell);
            float hx = hq[3 * qi + 0], hy = hq[3 * qi + 1], hz = hq[3 * qi + 2];
            float nxr = nq[3 * qi + 0], nyr = nq[3 * qi + 1], nzr = nq[3 * qi + 2];
            float npx = fmaf(R0, nxr, fmaf(R3, nyr, R6 * nzr));
            float npy = fmaf(R1, nxr, fmaf(R4, nyr, R7 * nzr));
            float npz = fmaf(R2, nxr, fmaf(R5, nyr, R8 * nzr));
            float rqv = rq[qi];
#pragma unroll
            for (int k = 0; k < KK; k++) {
                int idx = (int)(__float_as_uint(keys[k]) & 0x1FFFu);
                int g3 = 3 * (boff + idx);
                float dx = qpx - xdbr[g3 + 0];
                float dy = qpy - xdbr[g3 + 1];
                float dz = qpz - xdbr[g3 + 2];
                float d2 = fmaf(dx, dx, fmaf(dy, dy, dz * dz));
                float ndot = fmaf(npx, ndbr[g3 + 0],
                                  fmaf(npy, ndbr[g3 + 1], npz * ndbr[g3 + 2]));
                float chx = hx - hdb[g3 + 0];
                float chy = hy - hdb[g3 + 1];
                float chz = hz - hdb[g3 + 2];
                float cd = sqrtf(fmaf(chx, chx, fmaf(chy, chy, chz * chz)) + 1e-12f);
                float rk = rdb[boff + idx];
                float alpha = 0.2f / (0.1f + rqv + rk);
                float nk = fmaxf(ndot * alpha, 0.0f);
                sum += __expf(-(d2 * inv_ls + cd * 5.0f)) * nk;
            }
        }

        // Warp reduce + one double atomic per block; last block finalizes.
#pragma unroll
        for (int o = 16; o > 0; o >>= 1) sum += __shfl_down_sync(0xffffffffu, sum, o);
        if (lane == 0) {
            atomicAdd(&g_acc[s], (double)sum);
            __threadfence();
            unsigned done = atomicAdd(&g_done, 1u);
            if (done == (unsigned)(gridDim.x * gridDim.y) - 1u) {
                double s1 = (double)npts1[0] + (double)npts1[1];
                double s2 = (double)npts2[0] + (double)npts2[1];
                double k1 = g_acc[0] / (s1 * (double)KK);
                double k2 = g_acc[1] / (s2 * (double)KK);
                out[0] = (float)(0.5 * (k1 + k2));
            }
        }
    }
}

extern "C" void kernel_launch(void* const* d_in, const int* in_sizes, int n_in,
                              void* d_out, int out_size) {
    const float* xyz1    = (const float*)d_in[0];
    const float* xyz2    = (const float*)d_in[1];
    const float* hsv1    = (const float*)d_in[2];
    const float* hsv2    = (const float*)d_in[3];
    const float* normal1 = (const float*)d_in[4];
    const float* normal2 = (const float*)d_in[5];
    const float* nres1   = (const float*)d_in[6];
    const float* nres2   = (const float*)d_in[7];
    const float* R12     = (const float*)d_in[8];
    const float* t12     = (const float*)d_in[9];
    const float* R21     = (const float*)d_in[10];
    const float* t21     = (const float*)d_in[11];
    const int*   npts1   = (const int*)d_in[12];
    const int*   npts2   = (const int*)d_in[13];
    float* out = (float*)d_out;

    init_kernel<<<(4 * NC2 + 1023) / 1024, 1024>>>();
    dim3 bgrid(BB * PP / 256, 2);
    count2_kernel<<<bgrid, 256>>>(xyz1, xyz2, npts1, npts2);
    dim3 qgrid(BB * PP / QB, 2);
    query_kernel<<<qgrid, QB * NW>>>(xyz1, hsv1, normal1, nres1,
                                     xyz2, hsv2, normal2, nres2,
                                     R12, t12, R21, t21, npts1, npts2, out);
}

// round 9
// speedup vs baseline: 15.5727x; 1.1518x over previous
#include <cuda_runtime.h>
#include <math.h>

#define BB 2
#define PP 8192
#define KK 20
#define NBIN 256
#define ZLO 1.0f
#define ZSPAN 60.0f
#define BINW (ZSPAN / NBIN)
#define INVBINW (NBIN / ZSPAN)
#define DCAP2 25.0f     // 5 m search-radius cap (dropped terms < 3e-19)
#define LBUF 64
#define CTHRESH 24

__device__ double g_acc[2];
__device__ unsigned g_done;
__device__ int g_hist[8][NBIN];        // [set*2 + (0=db,1=query)]
__device__ int g_offs[8][NBIN + 1];
__device__ int g_curs[8][NBIN];
__device__ float4 g_dbp[4][PP];        // z-binned db points (x,y,z, idx bits)
__device__ float4 g_qp[4][PP];         // z-binned transformed queries (q'x,q'y,q'z, idx bits)

// Insert packed key x into 4 sorted chains of 5 (tails at 4,9,14,19).
#define CHAIN_INSERT(keys, x)                                                   \
    do {                                                                        \
        float tt0 = keys[4], tt1 = keys[9], tt2 = keys[14], tt3 = keys[19];     \
        int sel_ = 0; float bv_ = tt0;                                          \
        if (tt1 > bv_) { bv_ = tt1; sel_ = 1; }                                 \
        if (tt2 > bv_) { bv_ = tt2; sel_ = 2; }                                 \
        if (tt3 > bv_) { bv_ = tt3; sel_ = 3; }                                 \
        float x0_ = (sel_ == 0) ? (x) : 3.3e38f;                                \
        float x1_ = (sel_ == 1) ? (x) : 3.3e38f;                                \
        float x2_ = (sel_ == 2) ? (x) : 3.3e38f;                                \
        float x3_ = (sel_ == 3) ? (x) : 3.3e38f;                                \
        _Pragma("unroll")                                                       \
        for (int k_ = 0; k_ < 5; k_++) {                                        \
            float lo_ = fminf(x0_, keys[k_]); x0_ = fmaxf(x0_, keys[k_]); keys[k_] = lo_; } \
        _Pragma("unroll")                                                       \
        for (int k_ = 5; k_ < 10; k_++) {                                       \
            float lo_ = fminf(x1_, keys[k_]); x1_ = fmaxf(x1_, keys[k_]); keys[k_] = lo_; } \
        _Pragma("unroll")                                                       \
        for (int k_ = 10; k_ < 15; k_++) {                                      \
            float lo_ = fminf(x2_, keys[k_]); x2_ = fmaxf(x2_, keys[k_]); keys[k_] = lo_; } \
        _Pragma("unroll")                                                       \
        for (int k_ = 15; k_ < 20; k_++) {                                      \
            float lo_ = fminf(x3_, keys[k_]); x3_ = fmaxf(x3_, keys[k_]); keys[k_] = lo_; } \
    } while (0)

__device__ __forceinline__ int zbin(float z) {
    return min(NBIN - 1, max(0, (int)floorf((z - ZLO) * INVBINW)));
}

__global__ void init_kernel() {
    int i = blockIdx.x * blockDim.x + threadIdx.x;
    if (i == 0) { g_acc[0] = 0.0; g_acc[1] = 0.0; g_done = 0u; }
    if (i < 8 * NBIN) ((int*)g_hist)[i] = 0;
}

// Histogram db points (raw z) and queries (q'z) per (side,batch) set.
__global__ void hist_kernel(const float* __restrict__ xyz1, const float* __restrict__ xyz2,
                            const float* __restrict__ R12, const float* __restrict__ t12,
                            const float* __restrict__ R21, const float* __restrict__ t21,
                            const int* __restrict__ npts1, const int* __restrict__ npts2) {
    const int s = blockIdx.y;
    const int gi = blockIdx.x * blockDim.x + threadIdx.x;
    const int b = gi >> 13;
    const int i = gi & (PP - 1);
    const int set = s * BB + b;
    const float* dbsrc = s ? xyz1 : xyz2;
    const int ldb = (s ? npts1 : npts2)[b];
    if (i < ldb)
        atomicAdd(&g_hist[set * 2][zbin(dbsrc[3 * gi + 2])], 1);
    const float* qsrc = s ? xyz2 : xyz1;
    const int lq = (s ? npts2 : npts1)[b];
    if (i < lq) {
        const float* Rm = (s ? R21 : R12) + b * 9;
        const float* tv = (s ? t21 : t12) + b * 3;
        float ux = qsrc[3 * gi + 0] - tv[0];
        float uy = qsrc[3 * gi + 1] - tv[1];
        float uz = qsrc[3 * gi + 2] - tv[2];
        float qpz = fmaf(Rm[2], ux, fmaf(Rm[5], uy, Rm[8] * uz));
        atomicAdd(&g_hist[set * 2 + 1][zbin(qpz)], 1);
    }
}

// Prefix-sum all 8 histograms; write offsets + scatter cursors.
__global__ void scan_kernel() {
    __shared__ int sv[NBIN];
    const int t = threadIdx.x;
    for (int a = 0; a < 8; a++) {
        int v = g_hist[a][t];
        sv[t] = v;
        __syncthreads();
        for (int o = 1; o < NBIN; o <<= 1) {
            int x = (t >= o) ? sv[t - o] : 0;
            __syncthreads();
            sv[t] += x;
            __syncthreads();
        }
        g_offs[a][t + 1] = sv[t];
        g_curs[a][t] = sv[t] - v;
        if (t == 0) g_offs[a][0] = 0;
        __syncthreads();
    }
}

// Scatter db points and transformed queries into bin-sorted arrays.
__global__ void scatter_kernel(const float* __restrict__ xyz1, const float* __restrict__ xyz2,
                               const float* __restrict__ R12, const float* __restrict__ t12,
                               const float* __restrict__ R21, const float* __restrict__ t21,
                               const int* __restrict__ npts1, const int* __restrict__ npts2) {
    const int s = blockIdx.y;
    const int gi = blockIdx.x * blockDim.x + threadIdx.x;
    const int b = gi >> 13;
    const int i = gi & (PP - 1);
    const int set = s * BB + b;
    const float* dbsrc = s ? xyz1 : xyz2;
    const int ldb = (s ? npts1 : npts2)[b];
    if (i < ldb) {
        float x = dbsrc[3 * gi + 0], y = dbsrc[3 * gi + 1], z = dbsrc[3 * gi + 2];
        int pos = atomicAdd(&g_curs[set * 2][zbin(z)], 1);
        g_dbp[set][pos] = make_float4(x, y, z, __int_as_float(i));
    }
    const float* qsrc = s ? xyz2 : xyz1;
    const int lq = (s ? npts2 : npts1)[b];
    if (i < lq) {
        const float* Rm = (s ? R21 : R12) + b * 9;
        const float* tv = (s ? t21 : t12) + b * 3;
        float ux = qsrc[3 * gi + 0] - tv[0];
        float uy = qsrc[3 * gi + 1] - tv[1];
        float uz = qsrc[3 * gi + 2] - tv[2];
        float qpx = fmaf(Rm[0], ux, fmaf(Rm[3], uy, Rm[6] * uz));
        float qpy = fmaf(Rm[1], ux, fmaf(Rm[4], uy, Rm[7] * uz));
        float qpz = fmaf(Rm[2], ux, fmaf(Rm[5], uy, Rm[8] * uz));
        int pos = atomicAdd(&g_curs[set * 2 + 1][zbin(qpz)], 1);
        g_qp[set][pos] = make_float4(qpx, qpy, qpz, __int_as_float(i));
    }
}

// Warp = 32 z-sorted queries; outward bin walk with ballot stop; local-buffer
// accepts with warp-synchronized compaction; exact epilogue.
__global__ __launch_bounds__(256) void query_kernel(
    const float* __restrict__ xyz1, const float* __restrict__ hsv1,
    const float* __restrict__ normal1, const float* __restrict__ nres1,
    const float* __restrict__ xyz2, const float* __restrict__ hsv2,
    const float* __restrict__ normal2, const float* __restrict__ nres2,
    const float* __restrict__ R12, const float* __restrict__ t12,
    const float* __restrict__ R21, const float* __restrict__ t21,
    const int* __restrict__ npts1, const int* __restrict__ npts2,
    float* __restrict__ out)
{
    const int set = blockIdx.y;
    const int s = set >> 1, b = set & 1;
    const int lane = threadIdx.x & 31;
    const int wid = threadIdx.x >> 5;
    const int boff = b * PP;

    const float* xq   = s ? xyz2 : xyz1;
    const float* hq   = s ? hsv2 : hsv1;
    const float* nq   = s ? normal2 : normal1;
    const float* rq   = s ? nres2 : nres1;
    const float* xdbr = s ? xyz1 : xyz2;
    const float* ndbr = s ? normal1 : normal2;
    const float* hdb  = s ? hsv1 : hsv2;
    const float* rdb  = s ? nres1 : nres2;
    const float* Rm   = (s ? R21 : R12) + b * 9;
    const int lq = (s ? npts2 : npts1)[b];

    float sum = 0.f;
    const int base = (blockIdx.x * 8 + wid) * 32;

    if (base < lq) {
        const int pos = base + lane;
        const bool act = pos < lq;
        float4 qr = g_qp[set][act ? pos : base];
        const float qpx = qr.x, qpy = qr.y, qpz = qr.z;
        const int iq = __float_as_int(qr.w);

        float keys[KK];
#pragma unroll
        for (int k = 0; k < KK; k++) keys[k] = 3.0e38f;
        float thr_l = act ? DCAP2 : -1.0f;
        int cnt = 0;
        unsigned lbuf[LBUF];   // local memory candidate buffer

        auto compact = [&]() {
            for (int e = 0; e < cnt; ++e) {
                float xk = __uint_as_float(lbuf[e]);
                CHAIN_INSERT(keys, xk);
            }
            cnt = 0;
            float tail = fmaxf(fmaxf(keys[4], keys[9]), fmaxf(keys[14], keys[19]));
            if (act) thr_l = fminf(tail * 1.002f, DCAP2);
        };

        const int dbarr = set * 2;
        auto procbin = [&](int bin) {
            int j0 = g_offs[dbarr][bin];
            int j1 = g_offs[dbarr][bin + 1];
            for (int j = j0; j < j1; ++j) {
                float4 p = g_dbp[set][j];     // same addr all lanes: broadcast
                float dx = qpx - p.x, dy = qpy - p.y, dz = qpz - p.z;
                float d2 = fmaf(dx, dx, fmaf(dy, dy, dz * dz));
                if (d2 < thr_l) {
                    unsigned key = (__float_as_uint(d2) & 0xFFFFE000u)
                                 | (unsigned)__float_as_int(p.w);
                    if (cnt < LBUF) lbuf[cnt++] = key;
                    else { float xk = __uint_as_float(key); CHAIN_INSERT(keys, xk); }
                }
            }
        };

        auto laneneed = [&](int bin) -> bool {
            float loe = ZLO + (float)bin * BINW;
            float hie = loe + BINW;
            float dz = fmaxf(fmaxf(loe - qpz, qpz - hie), 0.f);
            return dz * dz < thr_l;          // thr_l=-1 for inactive -> false
        };

        int cb = zbin(qpz);
        int cbm = act ? cb : 0x7fffffff;
        int cbx = act ? cb : (int)0x80000000;
#pragma unroll
        for (int o = 16; o; o >>= 1) {
            cbm = min(cbm, __shfl_xor_sync(0xffffffffu, cbm, o));
            cbx = max(cbx, __shfl_xor_sync(0xffffffffu, cbx, o));
        }

        for (int bin = cbm; bin <= cbx; ++bin) {
            procbin(bin);
            if (__ballot_sync(0xffffffffu, cnt >= CTHRESH)) compact();
        }
        int dn = cbm - 1, up = cbx + 1;
        for (int it = 0; it < NBIN; ++it) {
            unsigned ndn = (dn >= 0)   ? __ballot_sync(0xffffffffu, laneneed(dn)) : 0u;
            unsigned nup = (up < NBIN) ? __ballot_sync(0xffffffffu, laneneed(up)) : 0u;
            if (!ndn && !nup) break;
            if (ndn) { procbin(dn); dn--; }
            if (nup) { procbin(up); up++; }
            if (__ballot_sync(0xffffffffu, cnt >= CTHRESH)) compact();
        }
        compact();

        // Exact epilogue over winners (skip sentinels: <20 found within cap).
        if (act) {
            const int qi = boff + iq;
            const float qz_own = xq[3 * qi + 2];
            float ell = fmaxf(0.015f * (qz_own - 10.0f), 0.15f);
            float inv_ls = 1.0f / (ell * ell);
            float hx = hq[3 * qi + 0], hy = hq[3 * qi + 1], hz = hq[3 * qi + 2];
            float nxr = nq[3 * qi + 0], nyr = nq[3 * qi + 1], nzr = nq[3 * qi + 2];
            float npx = fmaf(Rm[0], nxr, fmaf(Rm[3], nyr, Rm[6] * nzr));
            float npy = fmaf(Rm[1], nxr, fmaf(Rm[4], nyr, Rm[7] * nzr));
            float npz = fmaf(Rm[2], nxr, fmaf(Rm[5], nyr, Rm[8] * nzr));
            float rqv = rq[qi];
#pragma unroll
            for (int k = 0; k < KK; k++) {
                if (keys[k] < 1.0e30f) {
                    int idx = (int)(__float_as_uint(keys[k]) & 0x1FFFu);
                    int g3 = 3 * (boff + idx);
                    float dx = qpx - xdbr[g3 + 0];
                    float dy = qpy - xdbr[g3 + 1];
                    float dz = qpz - xdbr[g3 + 2];
                    float d2 = fmaf(dx, dx, fmaf(dy, dy, dz * dz));
                    float ndot = fmaf(npx, ndbr[g3 + 0],
                                      fmaf(npy, ndbr[g3 + 1], npz * ndbr[g3 + 2]));
                    float chx = hx - hdb[g3 + 0];
                    float chy = hy - hdb[g3 + 1];
                    float chz = hz - hdb[g3 + 2];
                    float cd = sqrtf(fmaf(chx, chx, fmaf(chy, chy, chz * chz)) + 1e-12f);
                    float rk = rdb[boff + idx];
                    float alpha = 0.2f / (0.1f + rqv + rk);
                    float nk = fmaxf(ndot * alpha, 0.0f);
                    sum += __expf(-(d2 * inv_ls + cd * 5.0f)) * nk;
                }
            }
        }
    }

    // Block reduce + single double atomic; last block finalizes.
#pragma unroll
    for (int o = 16; o > 0; o >>= 1) sum += __shfl_down_sync(0xffffffffu, sum, o);
    __shared__ float wsum[8];
    if (lane == 0) wsum[wid] = sum;
    __syncthreads();
    if (threadIdx.x == 0) {
        float bs = 0.f;
#pragma unroll
        for (int w2 = 0; w2 < 8; w2++) bs += wsum[w2];
        atomicAdd(&g_acc[s], (double)bs);
        __threadfence();
        unsigned done = atomicAdd(&g_done, 1u);
        if (done == (unsigned)(gridDim.x * gridDim.y) - 1u) {
            double s1 = (double)npts1[0] + (double)npts1[1];
            double s2 = (double)npts2[0] + (double)npts2[1];
            double k1 = g_acc[0] / (s1 * (double)KK);
            double k2 = g_acc[1] / (s2 * (double)KK);
            out[0] = (float)(0.5 * (k1 + k2));
        }
    }
}

extern "C" void kernel_launch(void* const* d_in, const int* in_sizes, int n_in,
                              void* d_out, int out_size) {
    const float* xyz1    = (const float*)d_in[0];
    const float* xyz2    = (const float*)d_in[1];
    const float* hsv1    = (const float*)d_in[2];
    const float* hsv2    = (const float*)d_in[3];
    const float* normal1 = (const float*)d_in[4];
    const float* normal2 = (const float*)d_in[5];
    const float* nres1   = (const float*)d_in[6];
    const float* nres2   = (const float*)d_in[7];
    const float* R12     = (const float*)d_in[8];
    const float* t12     = (const float*)d_in[9];
    const float* R21     = (const float*)d_in[10];
    const float* t21     = (const float*)d_in[11];
    const int*   npts1   = (const int*)d_in[12];
    const int*   npts2   = (const int*)d_in[13];
    float* out = (float*)d_out;

    init_kernel<<<2, 1024>>>();
    dim3 bgrid(BB * PP / 256, 2);
    hist_kernel<<<bgrid, 256>>>(xyz1, xyz2, R12, t12, R21, t21, npts1, npts2);
    scan_kernel<<<1, NBIN>>>();
    scatter_kernel<<<bgrid, 256>>>(xyz1, xyz2, R12, t12, R21, t21, npts1, npts2);
    dim3 qgrid(32, 4);
    query_kernel<<<qgrid, 256>>>(xyz1, hsv1, normal1, nres1,
                                 xyz2, hsv2, normal2, nres2,
                                 R12, t12, R21, t21, npts1, npts2, out);
}